// round 6
// baseline (speedup 1.0000x reference)
#include <cuda_runtime.h>
#include <math.h>

#define B_ 4
#define C_ 128
#define H_ 8
#define DH_ 16
#define F_ 4096
#define NR_ 127
#define NS_ 16      // key-split chunks
#define CK_ 256     // keys per chunk
#define SMAX_ 64

typedef unsigned long long ull;

// ------------------------- packed f32x2 helpers ----------------------------
__device__ __forceinline__ ull pk2(float lo, float hi) {
    ull r; asm("mov.b64 %0, {%1, %2};" : "=l"(r) : "f"(lo), "f"(hi)); return r;
}
__device__ __forceinline__ void upk2(ull v, float& lo, float& hi) {
    asm("mov.b64 {%0, %1}, %2;" : "=f"(lo), "=f"(hi) : "l"(v));
}
__device__ __forceinline__ ull fma2(ull a, ull b, ull c) {
    ull d; asm("fma.rn.f32x2 %0, %1, %2, %3;" : "=l"(d) : "l"(a), "l"(b), "l"(c)); return d;
}
__device__ __forceinline__ ull add2(ull a, ull b) {
    ull d; asm("add.rn.f32x2 %0, %1, %2;" : "=l"(d) : "l"(a), "l"(b)); return d;
}
__device__ __forceinline__ float ex2(float x) {
    float y; asm("ex2.approx.ftz.f32 %0, %1;" : "=f"(y) : "f"(x)); return y;
}

// ----------------------------- scratch ------------------------------------
__device__ float g_Q[B_*H_*F_*DH_];                 // (b,h,n,d) 8 MB
__device__ float g_K[B_*H_*F_*DH_];
__device__ float g_V[B_*H_*F_*DH_];
__device__ float g_L[2][B_*H_*NS_*SMAX_];
__device__ float g_O[2][B_*H_*NS_*SMAX_*DH_];
__device__ float g_va[B_*C_];                       // Wv0 @ anchor
__device__ float g_k1[B_*H_*DH_];                   // normalized Wk1 @ anchor

// --------------------- prologue: Q/K/V = W @ x -----------------------------
// grid (F/32, 3, B), block 256 = 32 cols x 8 heads
__global__ void proj_kernel(const float* __restrict__ x,
                            const float* __restrict__ Wq,
                            const float* __restrict__ Wk,
                            const float* __restrict__ Wv) {
    __shared__ float WsT[64][132];
    const float* W   = (blockIdx.y == 0) ? Wq  : (blockIdx.y == 1 ? Wk  : Wv);
    float*       out = (blockIdx.y == 0) ? g_Q : (blockIdx.y == 1 ? g_K : g_V);
    const int b  = blockIdx.z;
    const int t  = threadIdx.x;
    const int tx = t & 31;
    const int ty = t >> 5;
    const int n  = blockIdx.x * 32 + tx;

    float acc[16];
#pragma unroll
    for (int i = 0; i < 16; i++) acc[i] = 0.f;

    for (int half = 0; half < 2; half++) {
        __syncthreads();
        for (int idx = t; idx < 64 * 128; idx += 256) {
            int co = idx >> 6, c = idx & 63;
            WsT[c][co] = W[co * 128 + half * 64 + c];
        }
        __syncthreads();
#pragma unroll 4
        for (int c = 0; c < 64; c++) {
            float xv = x[((size_t)(b * 128 + half * 64 + c)) * 4096 + n];
            const float4* wr = (const float4*)&WsT[c][ty * 16];
            float4 w0 = wr[0], w1 = wr[1], w2 = wr[2], w3 = wr[3];
            acc[0]  += w0.x * xv;  acc[1]  += w0.y * xv;
            acc[2]  += w0.z * xv;  acc[3]  += w0.w * xv;
            acc[4]  += w1.x * xv;  acc[5]  += w1.y * xv;
            acc[6]  += w1.z * xv;  acc[7]  += w1.w * xv;
            acc[8]  += w2.x * xv;  acc[9]  += w2.y * xv;
            acc[10] += w2.z * xv;  acc[11] += w2.w * xv;
            acc[12] += w3.x * xv;  acc[13] += w3.y * xv;
            acc[14] += w3.z * xv;  acc[15] += w3.w * xv;
        }
    }
    float4* dst = (float4*)&out[(((size_t)b * 8 + ty) * 4096 + n) * 16];
    dst[0] = make_float4(acc[0],  acc[1],  acc[2],  acc[3]);
    dst[1] = make_float4(acc[4],  acc[5],  acc[6],  acc[7]);
    dst[2] = make_float4(acc[8],  acc[9],  acc[10], acc[11]);
    dst[3] = make_float4(acc[12], acc[13], acc[14], acc[15]);
}

// ----------------- per-ring attention partial + lazy patch -----------------
struct PatchSm {
    float Wk[16][129];
    float Wv[16][129];
    float fc[5][129];
};
struct MergeSm {
    float L[256];        // [qi * nsub + sub]
    float O[4416];       // [qi * strideO + sub*17 + d], strideO = nsub*17+1
};
union SmU { PatchSm p; MergeSm m; };

// grid (NS_, H_, B_), block 256
__global__ void __launch_bounds__(256, 4)
attn_partial(int r,
             const float* __restrict__ x,
             const float* __restrict__ Wk0,
             const float* __restrict__ Wv0,
             float* __restrict__ feats_out) {
    __shared__ SmU sm;
    const int cs = blockIdx.x, h = blockIdx.y, b = blockIdx.z;
    const int t = threadIdx.x;
    const int lo = max(0, r - 63), hi = min(r, 63), s = hi - lo + 1;
    const int par  = r & 1;
    const int par1 = par ^ 1;

    // ---- phase 1: combine ring r-1 partials (plain sums); patch K/V ----
    if (r > 0) {
        const int rm  = r - 1;
        const int lo1 = max(0, rm - 63), hi1 = min(rm, 63);
        int a = cs * 256 - rm;
        int imin = (a <= 0) ? lo1 : (a + 62) / 63;
        if (imin < lo1) imin = lo1;
        int imax = (cs * 256 + 255 - rm) / 63;
        if (imax > hi1) imax = hi1;
        const int np = imax - imin + 1;
        if (np > 0) {
            for (int idx = t; idx < 16 * 128; idx += 256) {
                int row = idx >> 7, c = idx & 127;
                sm.p.Wk[row][c] = Wk0[(h * 16 + row) * 128 + c];
                sm.p.Wv[row][c] = Wv0[(h * 16 + row) * 128 + c];
            }
            for (int idx = t; idx < np * 128; idx += 256) {
                int ci = idx >> 7, c = idx & 127;
                int hh = c >> 4, d = c & 15;
                int i  = imin + ci;
                int qi = i - lo1;
                int col = 63 * i + rm;
                int base = ((b * 8 + hh) * 16) * 64 + qi;
                float L = 0.f, O = 0.f;
#pragma unroll 4
                for (int ch = 0; ch < 16; ch++) {
                    int pidx = base + ch * 64;
                    L += g_L[par1][pidx];
                    O += g_O[par1][(size_t)pidx * 16 + d];
                }
                float f = x[((size_t)(b * 128 + c)) * 4096 + col] + O / L;
                sm.p.fc[ci][c] = f;
                if (h == 0)
                    feats_out[((size_t)(b * 128 + c)) * 4096 + col] = f;
            }
            __syncthreads();
            for (int w = t; w < np * 32; w += 256) {
                int which = w / (np * 16);          // 0->K, 1->V
                int m2 = w % (np * 16);
                int ci = m2 >> 4, row = m2 & 15;
                float accp = 0.f;
                if (which == 0) {
#pragma unroll 8
                    for (int c = 0; c < 128; c++) accp += sm.p.Wk[row][c] * sm.p.fc[ci][c];
                } else {
#pragma unroll 8
                    for (int c = 0; c < 128; c++) accp += sm.p.Wv[row][c] * sm.p.fc[ci][c];
                }
                int col = 63 * (imin + ci) + rm;
                float* dst = which ? g_V : g_K;
                dst[(((size_t)b * 8 + h) * 4096 + col) * 16 + row] = accp;
            }
        }
        __syncthreads();   // patched K/V visible block-wide before compute
    }

    // ---- s-adaptive work mapping ----
    int qShift, nsub;
    if (s > 32)      { qShift = 6; nsub = 4;  }
    else if (s > 16) { qShift = 5; nsub = 8;  }
    else             { qShift = 4; nsub = 16; }
    const int qSlots  = 1 << qShift;
    const int kps     = CK_ >> (8 - qShift);   // 64 / 32 / 16 keys per sub
    const int qi      = t & (qSlots - 1);
    const int sub     = t >> qShift;
    const int strideO = nsub * 17 + 1;
    const bool act    = (qi < s);

    // ---- phase 2+3: direct-from-L2 fixed-max softmax partial ----
    const ull Z = 0ull;
    ull o2[8];
#pragma unroll
    for (int i = 0; i < 8; i++) o2[i] = Z;
    float l = 0.f;

    if (act) {
        const float CSC = 0.36067376022224085f;   // 0.25 * log2(e)
        ull q2[8];
        {
            const float4* Qr = (const float4*)
                &g_Q[(((size_t)b * 8 + h) * 4096 + 63 * (lo + qi) + r) * 16];
            float4 qa = Qr[0], qb = Qr[1], qc = Qr[2], qd = Qr[3];
            q2[0] = pk2(qa.x * CSC, qa.y * CSC);
            q2[1] = pk2(qa.z * CSC, qa.w * CSC);
            q2[2] = pk2(qb.x * CSC, qb.y * CSC);
            q2[3] = pk2(qb.z * CSC, qb.w * CSC);
            q2[4] = pk2(qc.x * CSC, qc.y * CSC);
            q2[5] = pk2(qc.z * CSC, qc.w * CSC);
            q2[6] = pk2(qd.x * CSC, qd.y * CSC);
            q2[7] = pk2(qd.z * CSC, qd.w * CSC);
        }

        const ulonglong2* Kg = (const ulonglong2*)
            &g_K[(((size_t)b * 8 + h) * 4096 + cs * CK_) * 16];
        const ulonglong2* Vg = (const ulonglong2*)
            &g_V[(((size_t)b * 8 + h) * 4096 + cs * CK_) * 16];

        const int j0 = sub * kps;
#pragma unroll 4
        for (int jj = 0; jj < kps; jj++) {
            const int j = j0 + jj;
            ulonglong2 k01 = Kg[j * 4 + 0], k23 = Kg[j * 4 + 1];
            ulonglong2 k45 = Kg[j * 4 + 2], k67 = Kg[j * 4 + 3];
            ull a0 = fma2(q2[0], k01.x, Z);
            ull a1 = fma2(q2[1], k01.y, Z);
            a0 = fma2(q2[2], k23.x, a0);
            a1 = fma2(q2[3], k23.y, a1);
            a0 = fma2(q2[4], k45.x, a0);
            a1 = fma2(q2[5], k45.y, a1);
            a0 = fma2(q2[6], k67.x, a0);
            a1 = fma2(q2[7], k67.y, a1);
            ull as = add2(a0, a1);
            float slo, shi; upk2(as, slo, shi);
            float p = ex2(slo + shi);
            l += p;
            ull p2 = pk2(p, p);
            ulonglong2 v01 = Vg[j * 4 + 0], v23 = Vg[j * 4 + 1];
            ulonglong2 v45 = Vg[j * 4 + 2], v67 = Vg[j * 4 + 3];
            o2[0] = fma2(p2, v01.x, o2[0]);
            o2[1] = fma2(p2, v01.y, o2[1]);
            o2[2] = fma2(p2, v23.x, o2[2]);
            o2[3] = fma2(p2, v23.y, o2[3]);
            o2[4] = fma2(p2, v45.x, o2[4]);
            o2[5] = fma2(p2, v45.y, o2[5]);
            o2[6] = fma2(p2, v67.x, o2[6]);
            o2[7] = fma2(p2, v67.y, o2[7]);
        }
    }

    // ---- phase 4: sum the nsub sub-partials per query (smem) ----
    __syncthreads();                   // patch smem no longer needed
    if (act) {
        sm.m.L[qi * nsub + sub] = l;
        float* Oq = &sm.m.O[qi * strideO + sub * 17];
#pragma unroll
        for (int i = 0; i < 8; i++) {
            float lo_, hi_; upk2(o2[i], lo_, hi_);
            Oq[2 * i]     = lo_;
            Oq[2 * i + 1] = hi_;
        }
    }
    __syncthreads();
    if (t < s) {
        float L = 0.f;
        float O[16];
#pragma unroll
        for (int d = 0; d < 16; d++) O[d] = 0.f;
        for (int u = 0; u < nsub; u++) {
            L += sm.m.L[t * nsub + u];
            const float* Oq = &sm.m.O[t * strideO + u * 17];
#pragma unroll
            for (int d = 0; d < 16; d++)
                O[d] += Oq[d];
        }
        int pidx = ((b * 8 + h) * 16 + cs) * 64 + t;
        g_L[par][pidx] = L;
        float4* dst = (float4*)&g_O[par][(size_t)pidx * 16];
        dst[0] = make_float4(O[0],  O[1],  O[2],  O[3]);
        dst[1] = make_float4(O[4],  O[5],  O[6],  O[7]);
        dst[2] = make_float4(O[8],  O[9],  O[10], O[11]);
        dst[3] = make_float4(O[12], O[13], O[14], O[15]);
    }
}

// ---------------- final combine for ring 126 -------------------------------
__global__ void combine_write(int r, const float* __restrict__ x,
                              float* __restrict__ feats_out) {
    const int b = blockIdx.y, qi = blockIdx.x, c = threadIdx.x;
    const int lo = max(0, r - 63);
    const int col = 63 * (lo + qi) + r;
    const int par = r & 1;
    const int hh = c >> 4, d = c & 15;
    int base = ((b * 8 + hh) * 16) * 64 + qi;
    float L = 0.f, O = 0.f;
#pragma unroll 4
    for (int ch = 0; ch < 16; ch++) {
        int pidx = base + ch * 64;
        L += g_L[par][pidx];
        O += g_O[par][(size_t)pidx * 16 + d];
    }
    feats_out[((size_t)(b * 128 + c)) * 4096 + col] =
        x[((size_t)(b * 128 + c)) * 4096 + col] + O / L;
}

// ---------------- epilogue 1 ------------------------------------------------
__global__ void epi1_kernel(const float* __restrict__ Wv0,
                            const float* __restrict__ Wk1,
                            const float* __restrict__ feats_out) {
    __shared__ float anc[128];
    __shared__ float k1raw[128];
    __shared__ float hs[8];
    const int b = blockIdx.x, t = threadIdx.x;
    anc[t] = feats_out[((size_t)(b * 128 + t)) * 4096 + 0];
    __syncthreads();
    float av = 0.f, kv = 0.f;
#pragma unroll 8
    for (int c = 0; c < 128; c++) {
        av += Wv0[t * 128 + c] * anc[c];
        kv += Wk1[t * 128 + c] * anc[c];
    }
    g_va[b * 128 + t] = av;
    k1raw[t] = kv;
    __syncthreads();
    if (t < 8) {
        float ss = 0.f;
#pragma unroll
        for (int d = 0; d < 16; d++) { float v = k1raw[t * 16 + d]; ss += v * v; }
        hs[t] = rsqrtf(ss + 1e-8f);
    }
    __syncthreads();
    g_k1[(b * 8 + (t >> 4)) * 16 + (t & 15)] = k1raw[t] * hs[t >> 4];
}

// ---------------- epilogue 2 ------------------------------------------------
__global__ void epi2_kernel(const float* __restrict__ x,
                            const float* __restrict__ Wq1,
                            float* __restrict__ scores_out) {
    __shared__ float WsT[64][132];
    __shared__ float sva[128];
    __shared__ float sred[8][32];
    const int b  = blockIdx.y;
    const int t  = threadIdx.x;
    const int tx = t & 31;
    const int ty = t >> 5;
    const int n  = blockIdx.x * 32 + tx;

    if (t < 128) sva[t] = g_va[b * 128 + t];

    float acc[16];
#pragma unroll
    for (int i = 0; i < 16; i++) acc[i] = 0.f;

    for (int half = 0; half < 2; half++) {
        __syncthreads();
        for (int idx = t; idx < 64 * 128; idx += 256) {
            int co = idx >> 6, c = idx & 63;
            WsT[c][co] = Wq1[co * 128 + half * 64 + c];
        }
        __syncthreads();
#pragma unroll 4
        for (int c = 0; c < 64; c++) {
            float qx = x[((size_t)(b * 128 + half * 64 + c)) * 4096 + n] + sva[half * 64 + c];
            const float4* wr = (const float4*)&WsT[c][ty * 16];
            float4 w0 = wr[0], w1 = wr[1], w2 = wr[2], w3 = wr[3];
            acc[0]  += w0.x * qx;  acc[1]  += w0.y * qx;
            acc[2]  += w0.z * qx;  acc[3]  += w0.w * qx;
            acc[4]  += w1.x * qx;  acc[5]  += w1.y * qx;
            acc[6]  += w1.z * qx;  acc[7]  += w1.w * qx;
            acc[8]  += w2.x * qx;  acc[9]  += w2.y * qx;
            acc[10] += w2.z * qx;  acc[11] += w2.w * qx;
            acc[12] += w3.x * qx;  acc[13] += w3.y * qx;
            acc[14] += w3.z * qx;  acc[15] += w3.w * qx;
        }
    }
    float qq = 0.f, dot = 0.f;
#pragma unroll
    for (int d = 0; d < 16; d++) {
        qq  += acc[d] * acc[d];
        dot += acc[d] * g_k1[(b * 8 + ty) * 16 + d];
    }
    float m = dot * rsqrtf(qq + 1e-8f);
    sred[ty][tx] = (m + 1.0f) * 0.5f;
    __syncthreads();
    if (ty == 0) {
        float sum = 0.f;
#pragma unroll
        for (int hh = 0; hh < 8; hh++) sum += sred[hh][tx];
        scores_out[(size_t)b * 4096 + n] = sum * 0.125f;
    }
}

// ---------------------------------------------------------------------------
extern "C" void kernel_launch(void* const* d_in, const int* in_sizes, int n_in,
                              void* d_out, int out_size) {
    const float* x   = (const float*)d_in[0];
    const float* Wq0 = (const float*)d_in[1];
    const float* Wk0 = (const float*)d_in[2];
    const float* Wv0 = (const float*)d_in[3];
    const float* Wq1 = (const float*)d_in[4];
    const float* Wk1 = (const float*)d_in[5];
    float* feats_out  = (float*)d_out;
    float* scores_out = feats_out + (size_t)B_ * C_ * F_;

    proj_kernel<<<dim3(128, 3, B_), 256>>>(x, Wq0, Wk0, Wv0);

    for (int r = 0; r < NR_; r++) {
        attn_partial<<<dim3(NS_, H_, B_), 256>>>(r, x, Wk0, Wv0, feats_out);
    }
    combine_write<<<dim3(1, B_), 128>>>(126, x, feats_out);

    epi1_kernel<<<B_, 128>>>(Wv0, Wk1, feats_out);
    epi2_kernel<<<dim3(128, B_), 256>>>(x, Wq1, scores_out);
}

// round 7
// speedup vs baseline: 1.4439x; 1.4439x over previous
#include <cuda_runtime.h>
#include <math.h>

#define B_ 4
#define C_ 128
#define H_ 8
#define DH_ 16
#define F_ 4096
#define NR_ 127
#define NS_ 16      // key-split chunks
#define CK_ 256     // keys per chunk
#define SMAX_ 64

typedef unsigned long long ull;

// ------------------------- packed f32x2 helpers ----------------------------
__device__ __forceinline__ ull pk2(float lo, float hi) {
    ull r; asm("mov.b64 %0, {%1, %2};" : "=l"(r) : "f"(lo), "f"(hi)); return r;
}
__device__ __forceinline__ void upk2(ull v, float& lo, float& hi) {
    asm("mov.b64 {%0, %1}, %2;" : "=f"(lo), "=f"(hi) : "l"(v));
}
__device__ __forceinline__ ull fma2(ull a, ull b, ull c) {
    ull d; asm("fma.rn.f32x2 %0, %1, %2, %3;" : "=l"(d) : "l"(a), "l"(b), "l"(c)); return d;
}
__device__ __forceinline__ ull add2(ull a, ull b) {
    ull d; asm("add.rn.f32x2 %0, %1, %2;" : "=l"(d) : "l"(a), "l"(b)); return d;
}
__device__ __forceinline__ float ex2(float x) {
    float y; asm("ex2.approx.ftz.f32 %0, %1;" : "=f"(y) : "f"(x)); return y;
}

// ----------------------------- scratch ------------------------------------
__device__ float g_Q[B_*H_*F_*DH_];                 // (b,h,n,d) 8 MB
__device__ float g_K[B_*H_*F_*DH_];
__device__ float g_V[B_*H_*F_*DH_];
__device__ float g_L[2][B_*H_*NS_*SMAX_];
__device__ float g_O[2][B_*H_*NS_*SMAX_*DH_];
__device__ float g_va[B_*C_];                       // Wv0 @ anchor
__device__ float g_k1[B_*H_*DH_];                   // normalized Wk1 @ anchor

// --------------------- prologue: Q/K/V = W @ x -----------------------------
// grid (F/32, 3, B), block 256 = 32 cols x 8 heads
__global__ void proj_kernel(const float* __restrict__ x,
                            const float* __restrict__ Wq,
                            const float* __restrict__ Wk,
                            const float* __restrict__ Wv) {
    __shared__ float WsT[64][132];
    const float* W   = (blockIdx.y == 0) ? Wq  : (blockIdx.y == 1 ? Wk  : Wv);
    float*       out = (blockIdx.y == 0) ? g_Q : (blockIdx.y == 1 ? g_K : g_V);
    const int b  = blockIdx.z;
    const int t  = threadIdx.x;
    const int tx = t & 31;
    const int ty = t >> 5;
    const int n  = blockIdx.x * 32 + tx;

    float acc[16];
#pragma unroll
    for (int i = 0; i < 16; i++) acc[i] = 0.f;

    for (int half = 0; half < 2; half++) {
        __syncthreads();
        for (int idx = t; idx < 64 * 128; idx += 256) {
            int co = idx >> 6, c = idx & 63;
            WsT[c][co] = W[co * 128 + half * 64 + c];
        }
        __syncthreads();
#pragma unroll 4
        for (int c = 0; c < 64; c++) {
            float xv = x[((size_t)(b * 128 + half * 64 + c)) * 4096 + n];
            const float4* wr = (const float4*)&WsT[c][ty * 16];
            float4 w0 = wr[0], w1 = wr[1], w2 = wr[2], w3 = wr[3];
            acc[0]  += w0.x * xv;  acc[1]  += w0.y * xv;
            acc[2]  += w0.z * xv;  acc[3]  += w0.w * xv;
            acc[4]  += w1.x * xv;  acc[5]  += w1.y * xv;
            acc[6]  += w1.z * xv;  acc[7]  += w1.w * xv;
            acc[8]  += w2.x * xv;  acc[9]  += w2.y * xv;
            acc[10] += w2.z * xv;  acc[11] += w2.w * xv;
            acc[12] += w3.x * xv;  acc[13] += w3.y * xv;
            acc[14] += w3.z * xv;  acc[15] += w3.w * xv;
        }
    }
    float4* dst = (float4*)&out[(((size_t)b * 8 + ty) * 4096 + n) * 16];
    dst[0] = make_float4(acc[0],  acc[1],  acc[2],  acc[3]);
    dst[1] = make_float4(acc[4],  acc[5],  acc[6],  acc[7]);
    dst[2] = make_float4(acc[8],  acc[9],  acc[10], acc[11]);
    dst[3] = make_float4(acc[12], acc[13], acc[14], acc[15]);
}

// ----------------- per-ring attention partial + lazy patch -----------------
struct PatchSm {
    float Wk[16][129];
    float Wv[16][129];
    float fc[5][129];
};
struct AttnSm {
    float4 K4[CK_][4];      // 16 KB
    float4 V4[CK_][4];      // 16 KB
    float  q[SMAX_][16];    // 4 KB
};
struct MergeSm {            // aliases K4/V4 after phase-3 sync
    float L[256];           // [qi * nsub + sub]
    float O[4416];          // [qi * strideO + sub*17 + d]
};
union SmU { PatchSm p; AttnSm a; MergeSm m; };

// grid (NS_, H_, B_), block 256
__global__ void __launch_bounds__(256, 4)
attn_partial(int r,
             const float* __restrict__ x,
             const float* __restrict__ Wk0,
             const float* __restrict__ Wv0,
             float* __restrict__ feats_out) {
    __shared__ SmU sm;
    const int cs = blockIdx.x, h = blockIdx.y, b = blockIdx.z;
    const int t = threadIdx.x;
    const int lo = max(0, r - 63), hi = min(r, 63), s = hi - lo + 1;
    const int par  = r & 1;
    const int par1 = par ^ 1;

    // ---- phase 1: combine ring r-1 partials (plain sums); patch K/V ----
    if (r > 0) {
        const int rm  = r - 1;
        const int lo1 = max(0, rm - 63), hi1 = min(rm, 63);
        int a = cs * 256 - rm;
        int imin = (a <= 0) ? lo1 : (a + 62) / 63;
        if (imin < lo1) imin = lo1;
        int imax = (cs * 256 + 255 - rm) / 63;
        if (imax > hi1) imax = hi1;
        const int np = imax - imin + 1;
        if (np > 0) {
            for (int idx = t; idx < 16 * 128; idx += 256) {
                int row = idx >> 7, c = idx & 127;
                sm.p.Wk[row][c] = Wk0[(h * 16 + row) * 128 + c];
                sm.p.Wv[row][c] = Wv0[(h * 16 + row) * 128 + c];
            }
            for (int idx = t; idx < np * 128; idx += 256) {
                int ci = idx >> 7, c = idx & 127;
                int hh = c >> 4, d = c & 15;
                int i  = imin + ci;
                int qi = i - lo1;
                int col = 63 * i + rm;
                int base = ((b * 8 + hh) * 16) * 64 + qi;
                float L = 0.f, O = 0.f;
#pragma unroll 4
                for (int ch = 0; ch < 16; ch++) {
                    int pidx = base + ch * 64;
                    L += g_L[par1][pidx];
                    O += g_O[par1][(size_t)pidx * 16 + d];
                }
                float f = x[((size_t)(b * 128 + c)) * 4096 + col] + O / L;
                sm.p.fc[ci][c] = f;
                if (h == 0)
                    feats_out[((size_t)(b * 128 + c)) * 4096 + col] = f;
            }
            __syncthreads();
            for (int w = t; w < np * 32; w += 256) {
                int which = w / (np * 16);          // 0->K, 1->V
                int m2 = w % (np * 16);
                int ci = m2 >> 4, row = m2 & 15;
                float accp = 0.f;
                if (which == 0) {
#pragma unroll 8
                    for (int c = 0; c < 128; c++) accp += sm.p.Wk[row][c] * sm.p.fc[ci][c];
                } else {
#pragma unroll 8
                    for (int c = 0; c < 128; c++) accp += sm.p.Wv[row][c] * sm.p.fc[ci][c];
                }
                int col = 63 * (imin + ci) + rm;
                float* dst = which ? g_V : g_K;
                dst[(((size_t)b * 8 + h) * 4096 + col) * 16 + row] = accp;
            }
        }
        __syncthreads();   // patched K/V visible before restaging
    }

    // ---- phase 2: stage q, K-chunk, V-chunk into smem ----
    for (int idx = t; idx < s * 16; idx += 256) {
        int i = idx >> 4, d = idx & 15;
        int col = 63 * (lo + i) + r;
        sm.a.q[i][d] = g_Q[(((size_t)b * 8 + h) * 4096 + col) * 16 + d];
    }
    {
        const float4* K4 = (const float4*)&g_K[(((size_t)b * 8 + h) * 4096 + cs * CK_) * 16];
        const float4* V4 = (const float4*)&g_V[(((size_t)b * 8 + h) * 4096 + cs * CK_) * 16];
        float4* Kd = &sm.a.K4[0][0];
        float4* Vd = &sm.a.V4[0][0];
        for (int idx = t; idx < CK_ * 4; idx += 256) { Kd[idx] = K4[idx]; Vd[idx] = V4[idx]; }
    }
    __syncthreads();

    // ---- s-adaptive work mapping (qSlots = keys/thread = 1<<qShift) ----
    int qShift, nsub;
    if      (s > 32) { qShift = 6; nsub = 4;  }
    else if (s > 16) { qShift = 5; nsub = 8;  }
    else if (s > 8)  { qShift = 4; nsub = 16; }
    else if (s > 4)  { qShift = 3; nsub = 32; }
    else             { qShift = 2; nsub = 64; }
    const int qSlots  = 1 << qShift;
    const int kps     = qSlots;               // keys per sub-chunk
    const int qi      = t & (qSlots - 1);
    const int sub     = t >> qShift;
    const int strideO = nsub * 17 + 1;
    const bool act    = (qi < s);

    // ---- phase 3: fixed-max softmax partial over kps keys ----
    const ull Z = 0ull;
    ull o2[8];
#pragma unroll
    for (int i = 0; i < 8; i++) o2[i] = Z;
    float l = 0.f;

    if (act) {
        const float CSC = 0.36067376022224085f;   // 0.25 * log2(e)
        ull q2[8];
#pragma unroll
        for (int i = 0; i < 8; i++)
            q2[i] = pk2(sm.a.q[qi][2*i] * CSC, sm.a.q[qi][2*i+1] * CSC);

        const int j0 = sub * kps;
#pragma unroll 4
        for (int jj = 0; jj < kps; jj++) {
            const int j = j0 + jj;
            const ulonglong2* Kp = (const ulonglong2*)&sm.a.K4[j][0];
            ulonglong2 k01 = Kp[0], k23 = Kp[1], k45 = Kp[2], k67 = Kp[3];
            ull a0 = fma2(q2[0], k01.x, Z);
            ull a1 = fma2(q2[1], k01.y, Z);
            a0 = fma2(q2[2], k23.x, a0);
            a1 = fma2(q2[3], k23.y, a1);
            a0 = fma2(q2[4], k45.x, a0);
            a1 = fma2(q2[5], k45.y, a1);
            a0 = fma2(q2[6], k67.x, a0);
            a1 = fma2(q2[7], k67.y, a1);
            ull as = add2(a0, a1);
            float slo, shi; upk2(as, slo, shi);
            float p = ex2(slo + shi);
            l += p;
            ull p2 = pk2(p, p);
            const ulonglong2* Vp = (const ulonglong2*)&sm.a.V4[j][0];
            ulonglong2 v01 = Vp[0], v23 = Vp[1], v45 = Vp[2], v67 = Vp[3];
            o2[0] = fma2(p2, v01.x, o2[0]);
            o2[1] = fma2(p2, v01.y, o2[1]);
            o2[2] = fma2(p2, v23.x, o2[2]);
            o2[3] = fma2(p2, v23.y, o2[3]);
            o2[4] = fma2(p2, v45.x, o2[4]);
            o2[5] = fma2(p2, v45.y, o2[5]);
            o2[6] = fma2(p2, v67.x, o2[6]);
            o2[7] = fma2(p2, v67.y, o2[7]);
        }
    }

    // ---- phase 4: sum the nsub sub-partials per query (smem, aliased) ----
    __syncthreads();                   // all K/V reads done; safe to alias
    if (act) {
        sm.m.L[qi * nsub + sub] = l;
        float* Oq = &sm.m.O[qi * strideO + sub * 17];
#pragma unroll
        for (int i = 0; i < 8; i++) {
            float lo_, hi_; upk2(o2[i], lo_, hi_);
            Oq[2 * i]     = lo_;
            Oq[2 * i + 1] = hi_;
        }
    }
    __syncthreads();
    if (t < s) {
        float L = 0.f;
        float O[16];
#pragma unroll
        for (int d = 0; d < 16; d++) O[d] = 0.f;
        for (int u = 0; u < nsub; u++) {
            L += sm.m.L[t * nsub + u];
            const float* Oq = &sm.m.O[t * strideO + u * 17];
#pragma unroll
            for (int d = 0; d < 16; d++)
                O[d] += Oq[d];
        }
        int pidx = ((b * 8 + h) * 16 + cs) * 64 + t;
        g_L[par][pidx] = L;
        float4* dst = (float4*)&g_O[par][(size_t)pidx * 16];
        dst[0] = make_float4(O[0],  O[1],  O[2],  O[3]);
        dst[1] = make_float4(O[4],  O[5],  O[6],  O[7]);
        dst[2] = make_float4(O[8],  O[9],  O[10], O[11]);
        dst[3] = make_float4(O[12], O[13], O[14], O[15]);
    }
}

// ---------------- final combine for ring 126 -------------------------------
__global__ void combine_write(int r, const float* __restrict__ x,
                              float* __restrict__ feats_out) {
    const int b = blockIdx.y, qi = blockIdx.x, c = threadIdx.x;
    const int lo = max(0, r - 63);
    const int col = 63 * (lo + qi) + r;
    const int par = r & 1;
    const int hh = c >> 4, d = c & 15;
    int base = ((b * 8 + hh) * 16) * 64 + qi;
    float L = 0.f, O = 0.f;
#pragma unroll 4
    for (int ch = 0; ch < 16; ch++) {
        int pidx = base + ch * 64;
        L += g_L[par][pidx];
        O += g_O[par][(size_t)pidx * 16 + d];
    }
    feats_out[((size_t)(b * 128 + c)) * 4096 + col] =
        x[((size_t)(b * 128 + c)) * 4096 + col] + O / L;
}

// ---------------- epilogue 1 ------------------------------------------------
__global__ void epi1_kernel(const float* __restrict__ Wv0,
                            const float* __restrict__ Wk1,
                            const float* __restrict__ feats_out) {
    __shared__ float anc[128];
    __shared__ float k1raw[128];
    __shared__ float hs[8];
    const int b = blockIdx.x, t = threadIdx.x;
    anc[t] = feats_out[((size_t)(b * 128 + t)) * 4096 + 0];
    __syncthreads();
    float av = 0.f, kv = 0.f;
#pragma unroll 8
    for (int c = 0; c < 128; c++) {
        av += Wv0[t * 128 + c] * anc[c];
        kv += Wk1[t * 128 + c] * anc[c];
    }
    g_va[b * 128 + t] = av;
    k1raw[t] = kv;
    __syncthreads();
    if (t < 8) {
        float ss = 0.f;
#pragma unroll
        for (int d = 0; d < 16; d++) { float v = k1raw[t * 16 + d]; ss += v * v; }
        hs[t] = rsqrtf(ss + 1e-8f);
    }
    __syncthreads();
    g_k1[(b * 8 + (t >> 4)) * 16 + (t & 15)] = k1raw[t] * hs[t >> 4];
}

// ---------------- epilogue 2 ------------------------------------------------
__global__ void epi2_kernel(const float* __restrict__ x,
                            const float* __restrict__ Wq1,
                            float* __restrict__ scores_out) {
    __shared__ float WsT[64][132];
    __shared__ float sva[128];
    __shared__ float sred[8][32];
    const int b  = blockIdx.y;
    const int t  = threadIdx.x;
    const int tx = t & 31;
    const int ty = t >> 5;
    const int n  = blockIdx.x * 32 + tx;

    if (t < 128) sva[t] = g_va[b * 128 + t];

    float acc[16];
#pragma unroll
    for (int i = 0; i < 16; i++) acc[i] = 0.f;

    for (int half = 0; half < 2; half++) {
        __syncthreads();
        for (int idx = t; idx < 64 * 128; idx += 256) {
            int co = idx >> 6, c = idx & 63;
            WsT[c][co] = Wq1[co * 128 + half * 64 + c];
        }
        __syncthreads();
#pragma unroll 4
        for (int c = 0; c < 64; c++) {
            float qx = x[((size_t)(b * 128 + half * 64 + c)) * 4096 + n] + sva[half * 64 + c];
            const float4* wr = (const float4*)&WsT[c][ty * 16];
            float4 w0 = wr[0], w1 = wr[1], w2 = wr[2], w3 = wr[3];
            acc[0]  += w0.x * qx;  acc[1]  += w0.y * qx;
            acc[2]  += w0.z * qx;  acc[3]  += w0.w * qx;
            acc[4]  += w1.x * qx;  acc[5]  += w1.y * qx;
            acc[6]  += w1.z * qx;  acc[7]  += w1.w * qx;
            acc[8]  += w2.x * qx;  acc[9]  += w2.y * qx;
            acc[10] += w2.z * qx;  acc[11] += w2.w * qx;
            acc[12] += w3.x * qx;  acc[13] += w3.y * qx;
            acc[14] += w3.z * qx;  acc[15] += w3.w * qx;
        }
    }
    float qq = 0.f, dot = 0.f;
#pragma unroll
    for (int d = 0; d < 16; d++) {
        qq  += acc[d] * acc[d];
        dot += acc[d] * g_k1[(b * 8 + ty) * 16 + d];
    }
    float m = dot * rsqrtf(qq + 1e-8f);
    sred[ty][tx] = (m + 1.0f) * 0.5f;
    __syncthreads();
    if (ty == 0) {
        float sum = 0.f;
#pragma unroll
        for (int hh = 0; hh < 8; hh++) sum += sred[hh][tx];
        scores_out[(size_t)b * 4096 + n] = sum * 0.125f;
    }
}

// ---------------------------------------------------------------------------
extern "C" void kernel_launch(void* const* d_in, const int* in_sizes, int n_in,
                              void* d_out, int out_size) {
    const float* x   = (const float*)d_in[0];
    const float* Wq0 = (const float*)d_in[1];
    const float* Wk0 = (const float*)d_in[2];
    const float* Wv0 = (const float*)d_in[3];
    const float* Wq1 = (const float*)d_in[4];
    const float* Wk1 = (const float*)d_in[5];
    float* feats_out  = (float*)d_out;
    float* scores_out = feats_out + (size_t)B_ * C_ * F_;

    proj_kernel<<<dim3(128, 3, B_), 256>>>(x, Wq0, Wk0, Wv0);

    for (int r = 0; r < NR_; r++) {
        attn_partial<<<dim3(NS_, H_, B_), 256>>>(r, x, Wk0, Wv0, feats_out);
    }
    combine_write<<<dim3(1, B_), 128>>>(126, x, feats_out);

    epi1_kernel<<<B_, 128>>>(Wv0, Wk1, feats_out);
    epi2_kernel<<<dim3(128, B_), 256>>>(x, Wq1, scores_out);
}